// round 7
// baseline (speedup 1.0000x reference)
#include <cuda_runtime.h>

// LearnableWaveletTransform: depthwise 1D cross-correlation, 2 shared 96-tap
// filters over x[64,128,4096] fp32, pad=48 -> out (l,h) each [64,128,4097].
//
// R7: FFMA2 with filters packed in fp32 lanes. New vs R5:
//  - Window stored in smem PRE-DUPLICATED as (v,v) 64-bit pairs: inner refill
//    is one LDS.64 straight into the FFMA2 operand (no pack MOV).
//  - Manual strength reduction of the skew: s0 = tid*16 is 16-aligned, so
//    phys(s0+c) = phys(s0) + c + (c>>4). Pointers advance by +17 ull / outer
//    iter; all inner offsets are immediates -> zero inner-loop ALU.
//  - Inner body: LDS.64(w) + LDS.64(x) + 16 FFMA2  (~94% fma issues).

#define KW      96
#define PADW    48
#define TLEN    4096
#define TOUT    4097
#define NROWS   8192            // 64 * 128
#define NTHREADS 256
#define RPT     16
#define TILE    (NTHREADS * RPT)        // 4096
#define WINLEN  (TILE + KW)             // 4192
#define SKEWULL (WINLEN + (WINLEN >> 4))  // 4454 ull = 35.6 KB
#define HALFOFF ((long long)NROWS * (long long)TOUT)  // 33,562,624

typedef unsigned long long ull;

__device__ __forceinline__ ull ffma2(ull a, ull b, ull c) {
    ull d;
    asm("fma.rn.f32x2 %0, %1, %2, %3;" : "=l"(d) : "l"(a), "l"(b), "l"(c));
    return d;
}
__device__ __forceinline__ ull pack2(float lo, float hi) {
    ull r;
    asm("mov.b64 %0, {%1, %2};" : "=l"(r) : "f"(lo), "f"(hi));
    return r;
}
__device__ __forceinline__ void unpack2(ull v, float& lo, float& hi) {
    asm("mov.b64 {%0, %1}, %2;" : "=f"(lo), "=f"(hi) : "l"(v));
}

__global__ void __launch_bounds__(NTHREADS, 3)
wavelet_f32x2_r7(const float* __restrict__ x,
                 const float* __restrict__ hw,
                 const float* __restrict__ lw,
                 float* __restrict__ out)
{
    __shared__ ull sxd[SKEWULL];        // duplicated (v,v) window, ull-skewed
    __shared__ ull wp[KW];              // (l_w[k], h_w[k])

    const int row = blockIdx.x;
    const int tid = threadIdx.x;
    const long long xbase = (long long)row * TLEN;

    // Fill duplicated, skewed window: sxd[i + (i>>4)] = (v, v)
    for (int i = tid; i < WINLEN; i += NTHREADS) {
        int g = i - PADW;
        float v = (g >= 0 && g < TLEN) ? x[xbase + g] : 0.0f;
        sxd[i + (i >> 4)] = pack2(v, v);
    }
    if (tid < KW) wp[tid] = pack2(lw[tid], hw[tid]);
    __syncthreads();

    const int s0 = tid * RPT;                       // multiple of 16
    const ull* pw = sxd + s0 + (s0 >> 4);           // phys base for this thread

    // Register window (16 deep). phys(s0+j) = base + j for j<16.
    ull xd[RPT];
    #pragma unroll
    for (int j = 0; j < RPT; ++j) xd[j] = pw[j];

    ull acc[RPT];
    #pragma unroll
    for (int j = 0; j < RPT; ++j) acc[j] = 0ULL;

    // phys(s0 + 16 + kk + ki) = base + (16+kk) + (16+kk)/16 + ki
    // -> pointer advances by 17 per outer iter; inner offsets are immediates.
    const ull* pk  = pw + 17;
    const ull* pwk = wp;
    #pragma unroll 1
    for (int kk = 0; kk < KW; kk += RPT) {
        #pragma unroll
        for (int ki = 0; ki < RPT; ++ki) {
            ull w = pwk[ki];                        // LDS.64 broadcast
            #pragma unroll
            for (int j = 0; j < RPT; ++j)
                acc[j] = ffma2(xd[j], w, acc[j]);
            #pragma unroll
            for (int j = 0; j < RPT - 1; ++j) xd[j] = xd[j + 1];
            xd[RPT - 1] = pk[ki];                   // LDS.64 [R+imm], no ALU
        }
        pk  += 17;
        pwk += RPT;
    }

    float lacc[RPT], hacc[RPT];
    #pragma unroll
    for (int j = 0; j < RPT; ++j) unpack2(acc[j], lacc[j], hacc[j]);

    // Tail output t = 4096 (window sxd covers TILE..TILE+95)
    float tl = 0.0f, th = 0.0f;
    if (tid == NTHREADS - 1) {
        ull e = 0ULL;
        #pragma unroll 16
        for (int k = 0; k < KW; ++k) {
            int i = TILE + k;
            e = ffma2(sxd[i + (i >> 4)], wp[k], e);
        }
        unpack2(e, tl, th);
    }

    const long long obase = (long long)row * TOUT;
    float* sxf = reinterpret_cast<float*>(sxd);     // reuse as float staging

    // Stage l -> coalesced STG
    __syncthreads();
    #pragma unroll
    for (int j = 0; j < RPT; ++j) {
        int i = s0 + j;
        sxf[i + (i >> 4)] = lacc[j];                // stride-17: conflict-free
    }
    __syncthreads();
    #pragma unroll
    for (int j = 0; j < RPT; ++j) {
        int t = tid + j * NTHREADS;                 // lane-consecutive
        out[obase + t] = sxf[t + (t >> 4)];
    }

    // Stage h
    __syncthreads();
    #pragma unroll
    for (int j = 0; j < RPT; ++j) {
        int i = s0 + j;
        sxf[i + (i >> 4)] = hacc[j];
    }
    __syncthreads();
    #pragma unroll
    for (int j = 0; j < RPT; ++j) {
        int t = tid + j * NTHREADS;
        out[HALFOFF + obase + t] = sxf[t + (t >> 4)];
    }

    if (tid == NTHREADS - 1) {
        out[obase + TLEN]           = tl;
        out[HALFOFF + obase + TLEN] = th;
    }
}

extern "C" void kernel_launch(void* const* d_in, const int* in_sizes, int n_in,
                              void* d_out, int out_size) {
    // metadata order: x, h_w, l_w ; output: (l_outs, h_outs) concatenated
    const float* x  = (const float*)d_in[0];
    const float* hw = (const float*)d_in[1];
    const float* lw = (const float*)d_in[2];
    float* out = (float*)d_out;

    dim3 grid(NROWS);
    dim3 block(NTHREADS);
    wavelet_f32x2_r7<<<grid, block>>>(x, hw, lw, out);
}